// round 3
// baseline (speedup 1.0000x reference)
#include <cuda_runtime.h>

#define MM 4
#define LL 2
#define NSTATE 1296       // 6^4
#define NPAD 1332         // 36 blocks of 37
#define PTOT 2048         // B*N
#define DD 64
#define TPB 224           // 7 warps

// ---------------- device-global precomputed gate storage ----------------
__device__ __align__(16) float  g_BS[2][LL][3][NSTATE];   // [bs1/bs2][layer][m] 36x36 row-major
__device__ __align__(16) float  g_SQ[LL][MM][36];         // squeeze 6x6
__device__ __align__(16) float  g_DP[LL][MM][36];         // displacement 6x6
__device__ __align__(16) float2 g_DIAG[LL][3][NSTATE];    // fused 4-mode phase: rot1, rot2, kerr

// =======================================================================
// Precompute kernel: matrix exponentials of REAL generators + phase tables
// expm via scaling (2^-5) + 10-term Taylor + 5 squarings.
// =======================================================================
__global__ void precompute_kernel(const float* __restrict__ bs1,
                                  const float* __restrict__ sq_r,
                                  const float* __restrict__ bs2,
                                  const float* __restrict__ disp,
                                  const float* __restrict__ rot1,
                                  const float* __restrict__ rot2,
                                  const float* __restrict__ kerr)
{
    __shared__ float A[NSTATE], P[NSTATE], T[NSTATE];
    int tid = threadIdx.x, bd = blockDim.x;
    int b = blockIdx.x;

    if (b < 12) {
        // ---- one 36x36 beamsplitter expm per block ----
        int which = b / 6, r6 = b % 6, l = r6 / 3, m = r6 % 3;
        float theta = (which ? bs2 : bs1)[l * 3 + m];
        for (int i = tid; i < NSTATE; i += bd) {
            int R = i / 36, Cc = i % 36;
            int i1 = R / 6, i2 = R % 6, j1 = Cc / 6, j2 = Cc % 6;
            float g = 0.f;
            if (i1 == j1 + 1 && j2 == i2 + 1) g += sqrtf((float)((j1 + 1) * (i2 + 1)));
            if (j1 == i1 + 1 && i2 == j2 + 1) g -= sqrtf((float)((i1 + 1) * (j2 + 1)));
            float a = theta * g * (1.f / 32.f);
            A[i] = a; P[i] = a; T[i] = a + (R == Cc ? 1.f : 0.f);
        }
        __syncthreads();
        for (int j = 2; j <= 10; j++) {
            float inv = 1.f / (float)j;
            float nv[3]; int cnt = 0;
            for (int i = tid; i < NSTATE; i += bd) {
                int R = i / 36, Cc = i % 36;
                float s = 0.f;
                #pragma unroll 6
                for (int k = 0; k < 36; k++) s += P[R * 36 + k] * A[k * 36 + Cc];
                nv[cnt++] = s * inv;
            }
            __syncthreads();
            cnt = 0;
            for (int i = tid; i < NSTATE; i += bd) { P[i] = nv[cnt]; T[i] += nv[cnt]; cnt++; }
            __syncthreads();
        }
        for (int s = 0; s < 5; s++) {
            float nv[3]; int cnt = 0;
            for (int i = tid; i < NSTATE; i += bd) {
                int R = i / 36, Cc = i % 36;
                float acc = 0.f;
                #pragma unroll 6
                for (int k = 0; k < 36; k++) acc += T[R * 36 + k] * T[k * 36 + Cc];
                nv[cnt++] = acc;
            }
            __syncthreads();
            cnt = 0;
            for (int i = tid; i < NSTATE; i += bd) T[i] = nv[cnt++];
            __syncthreads();
        }
        for (int i = tid; i < NSTATE; i += bd) g_BS[which][l][m][i] = T[i];
    } else {
        // ---- block 12: sixteen 6x6 expms (lockstep) + fused phase tables ----
        bool act = tid < 576;
        int mid = tid / 36, e = tid % 36, r = e / 6, c = e % 6;
        if (act) {
            int l = (mid % 8) / 4, m = mid % 4;
            float theta, g = 0.f;
            if (mid < 8) {  // squeeze
                theta = sq_r[l * 4 + m];
                if (c == r + 2)      g =  0.5f * sqrtf((float)((r + 1) * (r + 2)));
                else if (r == c + 2) g = -0.5f * sqrtf((float)((c + 1) * (c + 2)));
            } else {        // displacement
                theta = disp[l * 4 + m];
                if (r == c + 1)      g =  sqrtf((float)(c + 1));
                else if (c == r + 1) g = -sqrtf((float)(r + 1));
            }
            float a = theta * g * (1.f / 32.f);
            A[tid] = a; P[tid] = a; T[tid] = a + (r == c ? 1.f : 0.f);
        }
        __syncthreads();
        for (int j = 2; j <= 10; j++) {
            float nv = 0.f;
            if (act) {
                float s = 0.f;
                #pragma unroll
                for (int k = 0; k < 6; k++) s += P[mid * 36 + r * 6 + k] * A[mid * 36 + k * 6 + c];
                nv = s / (float)j;
            }
            __syncthreads();
            if (act) { P[tid] = nv; T[tid] += nv; }
            __syncthreads();
        }
        for (int s = 0; s < 5; s++) {
            float nv = 0.f;
            if (act) {
                float acc = 0.f;
                #pragma unroll
                for (int k = 0; k < 6; k++) acc += T[mid * 36 + r * 6 + k] * T[mid * 36 + k * 6 + c];
                nv = acc;
            }
            __syncthreads();
            if (act) T[tid] = nv;
            __syncthreads();
        }
        if (act) {
            int l = (mid % 8) / 4, m = mid % 4;
            if (mid < 8) g_SQ[l][m][e] = T[tid];
            else         g_DP[l][m][e] = T[tid];
        }
        // fused 4-mode diagonal phase tables
        for (int t = tid; t < LL * 3 * NSTATE; t += bd) {
            int l = t / (3 * NSTATE), rem = t % (3 * NSTATE);
            int pass = rem / NSTATE, idx = rem % NSTATE;
            float n3 = (float)(idx % 6), n2 = (float)((idx / 6) % 6),
                  n1 = (float)((idx / 36) % 6), n0 = (float)(idx / 216);
            const float* par = (pass == 0) ? rot1 : (pass == 1) ? rot2 : kerr;
            float ang;
            if (pass < 2)
                ang = par[l*4+0]*n0 + par[l*4+1]*n1 + par[l*4+2]*n2 + par[l*4+3]*n3;
            else
                ang = par[l*4+0]*n0*n0 + par[l*4+1]*n1*n1 + par[l*4+2]*n2*n2 + par[l*4+3]*n3*n3;
            float sn, cs;
            sincosf(ang, &sn, &cs);
            g_DIAG[l][pass][idx] = make_float2(cs, sn);
        }
    }
}

// =======================================================================
// Main kernel: one block per state.
// State in shared memory, PADDED layout: logical index i lives at
// PL(i) = i + i/36  (36 blocks of 37 float2) -> bank-conflict-free for
// the worst-case stride-1-fiber gate, <=2-way for the rest.
// Gate matrices read directly from global (L1 broadcast).
// =======================================================================

__device__ __forceinline__ int PL(int i) { return i + i / 36; }

// two-mode gate (real 36x36) on fibers; out-of-place (ping-pong)
template <int S>
__device__ __forceinline__ void apply2_body(const float* __restrict__ U,
                                            const float2* __restrict__ in,
                                            float2* __restrict__ outp, int tid)
{
    if (tid < 216) {
        int g = tid / 36, f = tid - g * 36;
        int basei = (f / S) * (36 * S) + (f % S);
        int baseP = basei + basei / 36;
        const float4* U4 = (const float4*)(U + g * 216);
        float2 acc[6];
        #pragma unroll
        for (int t = 0; t < 6; t++) acc[t] = make_float2(0.f, 0.f);
        #pragma unroll
        for (int c = 0; c < 9; c++) {
            float2 x[4];
            #pragma unroll
            for (int j = 0; j < 4; j++) {
                const int cd = c * 4 + j;
                x[j] = in[baseP + cd * S + (cd * S) / 36];   // offset is compile-time const
            }
            #pragma unroll
            for (int t = 0; t < 6; t++) {
                float4 u = __ldg(U4 + t * 9 + c);
                acc[t].x = fmaf(u.x, x[0].x, acc[t].x);
                acc[t].y = fmaf(u.x, x[0].y, acc[t].y);
                acc[t].x = fmaf(u.y, x[1].x, acc[t].x);
                acc[t].y = fmaf(u.y, x[1].y, acc[t].y);
                acc[t].x = fmaf(u.z, x[2].x, acc[t].x);
                acc[t].y = fmaf(u.z, x[2].y, acc[t].y);
                acc[t].x = fmaf(u.w, x[3].x, acc[t].x);
                acc[t].y = fmaf(u.w, x[3].y, acc[t].y);
            }
        }
        #pragma unroll
        for (int t = 0; t < 6; t++) {
            int o = (g * 6 + t) * S;
            outp[baseP + o + o / 36] = acc[t];
        }
    }
}

// single-mode gate (real 6x6), in-place (fiber-exclusive, register-staged)
template <int S>
__device__ __forceinline__ void apply1_body(const float* __restrict__ Ug,
                                            float2* __restrict__ st, int tid)
{
    if (tid < 216) {
        int hi = tid / S, lo = tid - hi * S;
        int basei = hi * 6 * S + lo;
        int baseP = basei + basei / 36;
        float u[36];
        #pragma unroll
        for (int q = 0; q < 9; q++) {
            float4 v = __ldg((const float4*)Ug + q);
            u[q*4] = v.x; u[q*4+1] = v.y; u[q*4+2] = v.z; u[q*4+3] = v.w;
        }
        float2 x[6];
        #pragma unroll
        for (int k = 0; k < 6; k++) x[k] = st[baseP + k * S + (k * S) / 36];
        #pragma unroll
        for (int r = 0; r < 6; r++) {
            float ar = 0.f, ai = 0.f;
            #pragma unroll
            for (int k = 0; k < 6; k++) {
                ar = fmaf(u[r*6+k], x[k].x, ar);
                ai = fmaf(u[r*6+k], x[k].y, ai);
            }
            st[baseP + r * S + (r * S) / 36] = make_float2(ar, ai);
        }
    }
}

__global__ __launch_bounds__(TPB) void qnn_kernel(const float* __restrict__ patches,
                                                  const float* __restrict__ enc_w,
                                                  const float* __restrict__ enc_b,
                                                  const float* __restrict__ ro_w,
                                                  const float* __restrict__ ro_b,
                                                  float* __restrict__ out)
{
    __shared__ __align__(16) float2 sSt[2][NPAD];
    __shared__ float tA[144], tP[144], tT[144];
    __shared__ float sAlpha[4];
    __shared__ float sD0[4][6];
    __shared__ float sRed[4][8];
    __shared__ float sQ[4];
    __shared__ float sW[5];

    int tid = threadIdx.x;
    int p = blockIdx.x;

    if (tid < 5) sW[tid] = 2.f * sqrtf((float)(tid + 1));

    // ---- per-state displacement amplitudes: alpha = patches_row . enc_w^T + enc_b ----
    if (tid < 128) {
        int m = tid >> 5, lane = tid & 31;
        float v = patches[p * 64 + lane]      * enc_w[m * 64 + lane]
                + patches[p * 64 + lane + 32] * enc_w[m * 64 + lane + 32];
        #pragma unroll
        for (int o = 16; o; o >>= 1) v += __shfl_xor_sync(0xffffffffu, v, o);
        if (lane == 0) sAlpha[m] = v + enc_b[m];
    }
    __syncthreads();

    // ---- Denc = expm(alpha*(ad-a)), 4 matrices in parallel (threads 0..143) ----
    {
        bool act = tid < 144;
        int m = tid / 36, e = tid % 36, r = e / 6, c = e % 6;
        if (act) {
            float g = 0.f;
            if (r == c + 1)      g =  sqrtf((float)(c + 1));
            else if (c == r + 1) g = -sqrtf((float)(r + 1));
            float a = sAlpha[m] * g * (1.f / 32.f);
            tA[tid] = a; tP[tid] = a; tT[tid] = a + (r == c ? 1.f : 0.f);
        }
        __syncthreads();
        for (int j = 2; j <= 10; j++) {
            float nv = 0.f;
            if (act) {
                float s = 0.f;
                #pragma unroll
                for (int k = 0; k < 6; k++) s += tP[m * 36 + r * 6 + k] * tA[m * 36 + k * 6 + c];
                nv = s / (float)j;
            }
            __syncthreads();
            if (act) { tP[tid] = nv; tT[tid] += nv; }
            __syncthreads();
        }
        for (int s = 0; s < 5; s++) {
            float nv = 0.f;
            if (act) {
                float acc = 0.f;
                #pragma unroll
                for (int k = 0; k < 6; k++) acc += tT[m * 36 + r * 6 + k] * tT[m * 36 + k * 6 + c];
                nv = acc;
            }
            __syncthreads();
            if (act) tT[tid] = nv;
            __syncthreads();
        }
        if (act && c == 0) sD0[m][r] = tT[tid];   // only column 0 needed (vacuum input)
    }
    __syncthreads();

    // ---- initial state = outer product of displacement first columns (real) ----
    for (int i = tid; i < NSTATE; i += TPB) {
        int n3 = i % 6, n2 = (i / 6) % 6, n1 = (i / 36) % 6, n0 = i / 216;
        sSt[0][PL(i)] = make_float2(sD0[0][n0] * sD0[1][n1] * sD0[2][n2] * sD0[3][n3], 0.f);
    }

    int cur = 0;

    #define DO_APPLY2(W, L, M3, SS)                                        \
        __syncthreads();                                                   \
        apply2_body<SS>(g_BS[W][L][M3], sSt[cur], sSt[cur ^ 1], tid);      \
        cur ^= 1;

    #define DO_DIAG(L, PASS)                                               \
        __syncthreads();                                                   \
        {                                                                  \
            const float2* dg = &g_DIAG[L][PASS][0];                        \
            float2* st = sSt[cur];                                         \
            for (int i = tid; i < NSTATE; i += TPB) {                      \
                float2 ph = __ldg(dg + i);                                 \
                float2 s = st[PL(i)];                                      \
                st[PL(i)] = make_float2(s.x * ph.x - s.y * ph.y,           \
                                        s.x * ph.y + s.y * ph.x);          \
            }                                                              \
        }

    #define DO_APPLY1_ALL(SRC)                                 \
        __syncthreads();                                       \
        apply1_body<216>((SRC)[0], sSt[cur], tid);             \
        __syncthreads();                                       \
        apply1_body<36>((SRC)[1], sSt[cur], tid);              \
        __syncthreads();                                       \
        apply1_body<6>((SRC)[2], sSt[cur], tid);               \
        __syncthreads();                                       \
        apply1_body<1>((SRC)[3], sSt[cur], tid);

    for (int l = 0; l < LL; l++) {
        // interferometer 1
        DO_APPLY2(0, l, 0, 36);
        DO_APPLY2(0, l, 1, 6);
        DO_APPLY2(0, l, 2, 1);
        // rotations 1 (fused over modes)
        DO_DIAG(l, 0);
        // squeezing
        DO_APPLY1_ALL(g_SQ[l]);
        // interferometer 2
        DO_APPLY2(1, l, 0, 36);
        DO_APPLY2(1, l, 1, 6);
        DO_APPLY2(1, l, 2, 1);
        // rotations 2
        DO_DIAG(l, 1);
        // displacement
        DO_APPLY1_ALL(g_DP[l]);
        // Kerr
        DO_DIAG(l, 2);
    }

    // ---- quadrature expectations  <X_m> = sum 2*sqrt(n+1)*Re(conj(s_n) s_{n+1}) ----
    __syncthreads();
    {
        const float2* st = sSt[cur];
        float q0 = 0.f, q1 = 0.f, q2 = 0.f, q3 = 0.f;
        for (int i = tid; i < NSTATE; i += TPB) {
            int n3 = i % 6, n2 = (i / 6) % 6, n1 = (i / 36) % 6, n0 = i / 216;
            int pl = PL(i);
            float2 s0 = st[pl];
            if (n0 < 5) { float2 s = st[pl + 222]; q0 += sW[n0] * (s0.x * s.x + s0.y * s.y); }
            if (n1 < 5) { float2 s = st[pl + 37];  q1 += sW[n1] * (s0.x * s.x + s0.y * s.y); }
            if (n2 < 5) { float2 s = st[pl + 6];   q2 += sW[n2] * (s0.x * s.x + s0.y * s.y); }
            if (n3 < 5) { float2 s = st[pl + 1];   q3 += sW[n3] * (s0.x * s.x + s0.y * s.y); }
        }
        #pragma unroll
        for (int o = 16; o; o >>= 1) {
            q0 += __shfl_xor_sync(0xffffffffu, q0, o);
            q1 += __shfl_xor_sync(0xffffffffu, q1, o);
            q2 += __shfl_xor_sync(0xffffffffu, q2, o);
            q3 += __shfl_xor_sync(0xffffffffu, q3, o);
        }
        int w = tid >> 5, lane = tid & 31;
        if (lane == 0) { sRed[0][w] = q0; sRed[1][w] = q1; sRed[2][w] = q2; sRed[3][w] = q3; }
    }
    __syncthreads();
    if (tid < 4) {
        float s = 0.f;
        #pragma unroll
        for (int k = 0; k < 7; k++) s += sRed[tid][k];
        sQ[tid] = s;
    }
    __syncthreads();

    // ---- readout: out[p,d] = sum_m quad[m]*ro_w[d,m] + ro_b[d] ----
    if (tid < DD) {
        float o = ro_b[tid];
        #pragma unroll
        for (int m = 0; m < 4; m++) o = fmaf(sQ[m], ro_w[tid * 4 + m], o);
        out[p * DD + tid] = o;
    }
}

// =======================================================================
extern "C" void kernel_launch(void* const* d_in, const int* in_sizes, int n_in,
                              void* d_out, int out_size)
{
    const float* patches = (const float*)d_in[0];
    const float* enc_w   = (const float*)d_in[1];
    const float* enc_b   = (const float*)d_in[2];
    const float* bs1     = (const float*)d_in[3];
    const float* rot1    = (const float*)d_in[4];
    const float* sq_r    = (const float*)d_in[5];
    const float* bs2     = (const float*)d_in[6];
    const float* rot2    = (const float*)d_in[7];
    const float* disp    = (const float*)d_in[8];
    const float* kerr    = (const float*)d_in[9];
    const float* ro_w    = (const float*)d_in[10];
    const float* ro_b    = (const float*)d_in[11];

    precompute_kernel<<<13, 640>>>(bs1, sq_r, bs2, disp, rot1, rot2, kerr);
    qnn_kernel<<<PTOT, TPB>>>(patches, enc_w, enc_b, ro_w, ro_b, (float*)d_out);
}

// round 4
// speedup vs baseline: 1.1772x; 1.1772x over previous
#include <cuda_runtime.h>

#define MM 4
#define LL 2
#define NSTATE 1296       // 6^4
#define NPAD 1332         // 36 blocks of 37
#define PTOT 2048         // B*N
#define DD 64
#define TPB 224           // 7 warps

// ---------------- device-global precomputed gate storage ----------------
__device__ __align__(16) float  g_BS[2][LL][3][NSTATE];   // [bs1/bs2][layer][m] 36x36 row-major
__device__ __align__(16) float2 g_U1c[LL][2][MM][36];     // [layer][0=SQ,1=DP][mode] complex 6x6
                                                          //  (rot/kerr phases folded in)

// =======================================================================
// Precompute kernel: matrix exponentials of REAL generators.
// expm via scaling (2^-5) + 10-term Taylor + 5 squarings.
// Diagonal rot/kerr phases are folded into the 6x6 gates (complex output).
// =======================================================================
__global__ void precompute_kernel(const float* __restrict__ bs1,
                                  const float* __restrict__ sq_r,
                                  const float* __restrict__ bs2,
                                  const float* __restrict__ disp,
                                  const float* __restrict__ rot1,
                                  const float* __restrict__ rot2,
                                  const float* __restrict__ kerr)
{
    __shared__ float A[NSTATE], P[NSTATE], T[NSTATE];
    int tid = threadIdx.x, bd = blockDim.x;
    int b = blockIdx.x;

    if (b < 12) {
        // ---- one 36x36 beamsplitter expm per block ----
        int which = b / 6, r6 = b % 6, l = r6 / 3, m = r6 % 3;
        float theta = (which ? bs2 : bs1)[l * 3 + m];
        for (int i = tid; i < NSTATE; i += bd) {
            int R = i / 36, Cc = i % 36;
            int i1 = R / 6, i2 = R % 6, j1 = Cc / 6, j2 = Cc % 6;
            float g = 0.f;
            if (i1 == j1 + 1 && j2 == i2 + 1) g += sqrtf((float)((j1 + 1) * (i2 + 1)));
            if (j1 == i1 + 1 && i2 == j2 + 1) g -= sqrtf((float)((i1 + 1) * (j2 + 1)));
            float a = theta * g * (1.f / 32.f);
            A[i] = a; P[i] = a; T[i] = a + (R == Cc ? 1.f : 0.f);
        }
        __syncthreads();
        for (int j = 2; j <= 10; j++) {
            float inv = 1.f / (float)j;
            float nv[3]; int cnt = 0;
            for (int i = tid; i < NSTATE; i += bd) {
                int R = i / 36, Cc = i % 36;
                float s = 0.f;
                #pragma unroll 6
                for (int k = 0; k < 36; k++) s += P[R * 36 + k] * A[k * 36 + Cc];
                nv[cnt++] = s * inv;
            }
            __syncthreads();
            cnt = 0;
            for (int i = tid; i < NSTATE; i += bd) { P[i] = nv[cnt]; T[i] += nv[cnt]; cnt++; }
            __syncthreads();
        }
        for (int s = 0; s < 5; s++) {
            float nv[3]; int cnt = 0;
            for (int i = tid; i < NSTATE; i += bd) {
                int R = i / 36, Cc = i % 36;
                float acc = 0.f;
                #pragma unroll 6
                for (int k = 0; k < 36; k++) acc += T[R * 36 + k] * T[k * 36 + Cc];
                nv[cnt++] = acc;
            }
            __syncthreads();
            cnt = 0;
            for (int i = tid; i < NSTATE; i += bd) T[i] = nv[cnt++];
            __syncthreads();
        }
        for (int i = tid; i < NSTATE; i += bd) g_BS[which][l][m][i] = T[i];
    } else {
        // ---- block 12: sixteen 6x6 expms (lockstep), then fold diagonals ----
        bool act = tid < 576;
        int mid = tid / 36, e = tid % 36, r = e / 6, c = e % 6;
        if (act) {
            int l = (mid % 8) / 4, m = mid % 4;
            float theta, g = 0.f;
            if (mid < 8) {  // squeeze
                theta = sq_r[l * 4 + m];
                if (c == r + 2)      g =  0.5f * sqrtf((float)((r + 1) * (r + 2)));
                else if (r == c + 2) g = -0.5f * sqrtf((float)((c + 1) * (c + 2)));
            } else {        // displacement
                theta = disp[l * 4 + m];
                if (r == c + 1)      g =  sqrtf((float)(c + 1));
                else if (c == r + 1) g = -sqrtf((float)(r + 1));
            }
            float a = theta * g * (1.f / 32.f);
            A[tid] = a; P[tid] = a; T[tid] = a + (r == c ? 1.f : 0.f);
        }
        __syncthreads();
        for (int j = 2; j <= 10; j++) {
            float nv = 0.f;
            if (act) {
                float s = 0.f;
                #pragma unroll
                for (int k = 0; k < 6; k++) s += P[mid * 36 + r * 6 + k] * A[mid * 36 + k * 6 + c];
                nv = s / (float)j;
            }
            __syncthreads();
            if (act) { P[tid] = nv; T[tid] += nv; }
            __syncthreads();
        }
        for (int s = 0; s < 5; s++) {
            float nv = 0.f;
            if (act) {
                float acc = 0.f;
                #pragma unroll
                for (int k = 0; k < 6; k++) acc += T[mid * 36 + r * 6 + k] * T[mid * 36 + k * 6 + c];
                nv = acc;
            }
            __syncthreads();
            if (act) T[tid] = nv;
            __syncthreads();
        }
        if (act) {
            int l = (mid % 8) / 4, m = mid % 4;
            float ang, sn, cs;
            if (mid < 8) {  // SQc = SQ @ diag(e^{i rot1 c})
                ang = rot1[l * 4 + m] * (float)c;
                sincosf(ang, &sn, &cs);
                g_U1c[l][0][m][e] = make_float2(T[tid] * cs, T[tid] * sn);
            } else {        // DPc = diag(e^{i kerr r^2}) @ DP @ diag(e^{i rot2 c})
                ang = kerr[l * 4 + m] * (float)(r * r) + rot2[l * 4 + m] * (float)c;
                sincosf(ang, &sn, &cs);
                g_U1c[l][1][m][e] = make_float2(T[tid] * cs, T[tid] * sn);
            }
        }
    }
}

// =======================================================================
// Main kernel: one block per state. Padded state layout PL(i)=i+i/36
// (bank-conflict-free worst case). Gate matrices staged in smem with a
// 3-buffer / 1-sync-per-gate pipeline.
// =======================================================================

__device__ __forceinline__ int PL(int i) { return i + i / 36; }

// two-mode gate (real 36x36, smem) on fibers; out-of-place (ping-pong)
template <int S>
__device__ __forceinline__ void apply2_body(const float* __restrict__ U,
                                            const float2* __restrict__ in,
                                            float2* __restrict__ outp, int tid)
{
    if (tid < 216) {
        int g = tid / 36, f = tid - g * 36;
        int basei = (f / S) * (36 * S) + (f % S);
        int baseP = basei + basei / 36;
        const float4* U4 = (const float4*)(U + g * 216);
        float2 acc[6];
        #pragma unroll
        for (int t = 0; t < 6; t++) acc[t] = make_float2(0.f, 0.f);
        #pragma unroll
        for (int c = 0; c < 9; c++) {
            float2 x[4];
            #pragma unroll
            for (int j = 0; j < 4; j++) {
                const int cd = c * 4 + j;
                x[j] = in[baseP + cd * S + (cd * S) / 36];   // pad offset is compile-time
            }
            #pragma unroll
            for (int t = 0; t < 6; t++) {
                float4 u = U4[t * 9 + c];
                acc[t].x = fmaf(u.x, x[0].x, acc[t].x);
                acc[t].y = fmaf(u.x, x[0].y, acc[t].y);
                acc[t].x = fmaf(u.y, x[1].x, acc[t].x);
                acc[t].y = fmaf(u.y, x[1].y, acc[t].y);
                acc[t].x = fmaf(u.z, x[2].x, acc[t].x);
                acc[t].y = fmaf(u.z, x[2].y, acc[t].y);
                acc[t].x = fmaf(u.w, x[3].x, acc[t].x);
                acc[t].y = fmaf(u.w, x[3].y, acc[t].y);
            }
        }
        #pragma unroll
        for (int t = 0; t < 6; t++) {
            int o = (g * 6 + t) * S;
            outp[baseP + o + o / 36] = acc[t];
        }
    }
}

// single-mode COMPLEX gate (6x6, diag phases folded), in-place
template <int S>
__device__ __forceinline__ void apply1c_body(const float2* __restrict__ Uc,
                                             float2* __restrict__ st, int tid)
{
    if (tid < 216) {
        int hi = tid / S, lo = tid - hi * S;
        int basei = hi * 6 * S + lo;
        int baseP = basei + basei / 36;
        float2 x[6];
        #pragma unroll
        for (int k = 0; k < 6; k++) x[k] = st[baseP + k * S + (k * S) / 36];
        #pragma unroll
        for (int r = 0; r < 6; r++) {
            float ar = 0.f, ai = 0.f;
            #pragma unroll
            for (int k = 0; k < 6; k++) {
                float2 u = Uc[r * 6 + k];
                ar = fmaf(u.x, x[k].x, ar); ar = fmaf(-u.y, x[k].y, ar);
                ai = fmaf(u.x, x[k].y, ai); ai = fmaf( u.y, x[k].x, ai);
            }
            st[baseP + r * S + (r * S) / 36] = make_float2(ar, ai);
        }
    }
}

__global__ __launch_bounds__(TPB) void qnn_kernel(const float* __restrict__ patches,
                                                  const float* __restrict__ enc_w,
                                                  const float* __restrict__ enc_b,
                                                  const float* __restrict__ ro_w,
                                                  const float* __restrict__ ro_b,
                                                  float* __restrict__ out)
{
    __shared__ __align__(16) float2 sSt[2][NPAD];
    __shared__ __align__(16) float  sU[3][NSTATE];
    __shared__ __align__(16) float2 sU1c[576];   // [layer][type][mode][36]
    __shared__ float tA[144], tP[144], tT[144];
    __shared__ float sAlpha[4];
    __shared__ float sD0[4][6];
    __shared__ float sRed[4][8];
    __shared__ float sQ[4];
    __shared__ float sW[5];

    int tid = threadIdx.x;
    int p = blockIdx.x;

    if (tid < 5) sW[tid] = 2.f * sqrtf((float)(tid + 1));

    // ---- per-state displacement amplitudes: alpha = patches_row . enc_w^T + enc_b ----
    if (tid < 128) {
        int m = tid >> 5, lane = tid & 31;
        float v = patches[p * 64 + lane]      * enc_w[m * 64 + lane]
                + patches[p * 64 + lane + 32] * enc_w[m * 64 + lane + 32];
        #pragma unroll
        for (int o = 16; o; o >>= 1) v += __shfl_xor_sync(0xffffffffu, v, o);
        if (lane == 0) sAlpha[m] = v + enc_b[m];
    }
    // stage all folded 6x6 complex gates (one-time)
    for (int i = tid; i < 576; i += TPB) sU1c[i] = ((const float2*)g_U1c)[i];
    __syncthreads();

    // ---- Denc = expm(alpha*(ad-a)), 4 matrices in parallel (threads 0..143) ----
    {
        bool act = tid < 144;
        int m = tid / 36, e = tid % 36, r = e / 6, c = e % 6;
        if (act) {
            float g = 0.f;
            if (r == c + 1)      g =  sqrtf((float)(c + 1));
            else if (c == r + 1) g = -sqrtf((float)(r + 1));
            float a = sAlpha[m] * g * (1.f / 32.f);
            tA[tid] = a; tP[tid] = a; tT[tid] = a + (r == c ? 1.f : 0.f);
        }
        __syncthreads();
        for (int j = 2; j <= 10; j++) {
            float nv = 0.f;
            if (act) {
                float s = 0.f;
                #pragma unroll
                for (int k = 0; k < 6; k++) s += tP[m * 36 + r * 6 + k] * tA[m * 36 + k * 6 + c];
                nv = s / (float)j;
            }
            __syncthreads();
            if (act) { tP[tid] = nv; tT[tid] += nv; }
            __syncthreads();
        }
        for (int s = 0; s < 5; s++) {
            float nv = 0.f;
            if (act) {
                float acc = 0.f;
                #pragma unroll
                for (int k = 0; k < 6; k++) acc += tT[m * 36 + r * 6 + k] * tT[m * 36 + k * 6 + c];
                nv = acc;
            }
            __syncthreads();
            if (act) tT[tid] = nv;
            __syncthreads();
        }
        if (act && c == 0) sD0[m][r] = tT[tid];   // only column 0 needed (vacuum input)
    }
    __syncthreads();

    // ---- initial state = outer product of displacement first columns (real) ----
    for (int i = tid; i < NSTATE; i += TPB) {
        int n3 = i % 6, n2 = (i / 6) % 6, n1 = (i / 36) % 6, n0 = i / 216;
        sSt[0][PL(i)] = make_float2(sD0[0][n0] * sD0[1][n1] * sD0[2][n2] * sD0[3][n3], 0.f);
    }

    int cur = 0;

    // flattened gate order: k = l*6 + which*3 + m
    #define BSP(K) (&g_BS[((K) % 6) / 3][(K) / 6][(K) % 3][0])

    #define STAGE(BUF, SRC)                                               \
        { const float4* s4 = (const float4*)(SRC);                        \
          float4* d4 = (float4*)(BUF);                                    \
          for (int i = tid; i < 324; i += TPB) d4[i] = __ldg(s4 + i); }

    // stage next gate into the idle 3rd buffer, ONE sync, compute current
    #define GATE(K, SS)                                                   \
        { if ((K) < 11) STAGE(sU[((K) + 1) % 3], BSP((K) + 1));           \
          __syncthreads();                                                \
          apply2_body<SS>(sU[(K) % 3], sSt[cur], sSt[cur ^ 1], tid);      \
          cur ^= 1; }

    #define DO_APPLY1C(PTR)                                    \
        __syncthreads();                                       \
        apply1c_body<216>((PTR) + 0 * 36, sSt[cur], tid);      \
        __syncthreads();                                       \
        apply1c_body<36>((PTR) + 1 * 36, sSt[cur], tid);       \
        __syncthreads();                                       \
        apply1c_body<6>((PTR) + 2 * 36, sSt[cur], tid);        \
        __syncthreads();                                       \
        apply1c_body<1>((PTR) + 3 * 36, sSt[cur], tid);

    STAGE(sU[0], BSP(0));

    GATE(0, 36); GATE(1, 6); GATE(2, 1);
    DO_APPLY1C(sU1c + 0 * 144);            // layer 0: SQ (rot1 folded)
    GATE(3, 36); GATE(4, 6); GATE(5, 1);
    DO_APPLY1C(sU1c + 1 * 144);            // layer 0: DP (rot2 + kerr folded)
    GATE(6, 36); GATE(7, 6); GATE(8, 1);
    DO_APPLY1C(sU1c + 2 * 144);            // layer 1: SQ
    GATE(9, 36); GATE(10, 6); GATE(11, 1);
    DO_APPLY1C(sU1c + 3 * 144);            // layer 1: DP

    // ---- quadrature expectations  <X_m> = sum 2*sqrt(n+1)*Re(conj(s_n) s_{n+1}) ----
    __syncthreads();
    {
        const float2* st = sSt[cur];
        float q0 = 0.f, q1 = 0.f, q2 = 0.f, q3 = 0.f;
        for (int i = tid; i < NSTATE; i += TPB) {
            int n3 = i % 6, n2 = (i / 6) % 6, n1 = (i / 36) % 6, n0 = i / 216;
            int pl = PL(i);
            float2 s0 = st[pl];
            if (n0 < 5) { float2 s = st[pl + 222]; q0 += sW[n0] * (s0.x * s.x + s0.y * s.y); }
            if (n1 < 5) { float2 s = st[pl + 37];  q1 += sW[n1] * (s0.x * s.x + s0.y * s.y); }
            if (n2 < 5) { float2 s = st[pl + 6];   q2 += sW[n2] * (s0.x * s.x + s0.y * s.y); }
            if (n3 < 5) { float2 s = st[pl + 1];   q3 += sW[n3] * (s0.x * s.x + s0.y * s.y); }
        }
        #pragma unroll
        for (int o = 16; o; o >>= 1) {
            q0 += __shfl_xor_sync(0xffffffffu, q0, o);
            q1 += __shfl_xor_sync(0xffffffffu, q1, o);
            q2 += __shfl_xor_sync(0xffffffffu, q2, o);
            q3 += __shfl_xor_sync(0xffffffffu, q3, o);
        }
        int w = tid >> 5, lane = tid & 31;
        if (lane == 0) { sRed[0][w] = q0; sRed[1][w] = q1; sRed[2][w] = q2; sRed[3][w] = q3; }
    }
    __syncthreads();
    if (tid < 4) {
        float s = 0.f;
        #pragma unroll
        for (int k = 0; k < 7; k++) s += sRed[tid][k];
        sQ[tid] = s;
    }
    __syncthreads();

    // ---- readout: out[p,d] = sum_m quad[m]*ro_w[d,m] + ro_b[d] ----
    if (tid < DD) {
        float o = ro_b[tid];
        #pragma unroll
        for (int m = 0; m < 4; m++) o = fmaf(sQ[m], ro_w[tid * 4 + m], o);
        out[p * DD + tid] = o;
    }
}

// =======================================================================
extern "C" void kernel_launch(void* const* d_in, const int* in_sizes, int n_in,
                              void* d_out, int out_size)
{
    const float* patches = (const float*)d_in[0];
    const float* enc_w   = (const float*)d_in[1];
    const float* enc_b   = (const float*)d_in[2];
    const float* bs1     = (const float*)d_in[3];
    const float* rot1    = (const float*)d_in[4];
    const float* sq_r    = (const float*)d_in[5];
    const float* bs2     = (const float*)d_in[6];
    const float* rot2    = (const float*)d_in[7];
    const float* disp    = (const float*)d_in[8];
    const float* kerr    = (const float*)d_in[9];
    const float* ro_w    = (const float*)d_in[10];
    const float* ro_b    = (const float*)d_in[11];

    precompute_kernel<<<13, 640>>>(bs1, sq_r, bs2, disp, rot1, rot2, kerr);
    qnn_kernel<<<PTOT, TPB>>>(patches, enc_w, enc_b, ro_w, ro_b, (float*)d_out);
}

// round 5
// speedup vs baseline: 2.0118x; 1.7091x over previous
#include <cuda_runtime.h>

#define MM 4
#define LL 2
#define NSTATE 1296       // 6^4
#define SPAD 1332         // padded: 36 blocks of 37 float2
#define PTOT 2048
#define DD 64
#define NS 4              // states per CTA
#define TPB 160
#define NACT 144          // NS*36 compute threads

// packed block-diagonal BS gates: blocks n=0..10, sizes 1..6..1, each padded to 4 floats
__device__ __align__(16) float  g_BSp[12][164];
__device__ __align__(16) float2 g_U1c[LL][2][MM][36];  // folded complex 6x6 (SQ/DP)

__host__ __device__ __forceinline__ constexpr int OFFT(int n) {
    return n==0?0 : n==1?4 : n==2?8 : n==3?20 : n==4?36 : n==5?64
         : n==6?100 : n==7?128 : n==8?144 : n==9?156 : 160;
}

// =======================================================================
// Precompute: dense 36x36 expm per BS gate -> packed block-diagonal;
// sixteen 6x6 expms with rot/kerr phases folded (complex).
// =======================================================================
__global__ void precompute_kernel(const float* __restrict__ bs1,
                                  const float* __restrict__ sq_r,
                                  const float* __restrict__ bs2,
                                  const float* __restrict__ disp,
                                  const float* __restrict__ rot1,
                                  const float* __restrict__ rot2,
                                  const float* __restrict__ kerr)
{
    __shared__ float A[NSTATE], P[NSTATE], T[NSTATE];
    int tid = threadIdx.x, bd = blockDim.x;
    int b = blockIdx.x;

    if (b < 12) {
        // gate index k = b : l = b/6, half = (b%6)/3, m = b%3
        int l = b / 6, half = (b % 6) / 3, m = b % 3;
        float theta = (half ? bs2 : bs1)[l * 3 + m];
        for (int i = tid; i < NSTATE; i += bd) {
            int R = i / 36, Cc = i % 36;
            int i1 = R / 6, i2 = R % 6, j1 = Cc / 6, j2 = Cc % 6;
            float g = 0.f;
            if (i1 == j1 + 1 && j2 == i2 + 1) g += sqrtf((float)((j1 + 1) * (i2 + 1)));
            if (j1 == i1 + 1 && i2 == j2 + 1) g -= sqrtf((float)((i1 + 1) * (j2 + 1)));
            float a = theta * g * (1.f / 32.f);
            A[i] = a; P[i] = a; T[i] = a + (R == Cc ? 1.f : 0.f);
        }
        __syncthreads();
        for (int j = 2; j <= 10; j++) {
            float inv = 1.f / (float)j;
            float nv[3]; int cnt = 0;
            for (int i = tid; i < NSTATE; i += bd) {
                int R = i / 36, Cc = i % 36;
                float s = 0.f;
                #pragma unroll 6
                for (int k = 0; k < 36; k++) s += P[R * 36 + k] * A[k * 36 + Cc];
                nv[cnt++] = s * inv;
            }
            __syncthreads();
            cnt = 0;
            for (int i = tid; i < NSTATE; i += bd) { P[i] = nv[cnt]; T[i] += nv[cnt]; cnt++; }
            __syncthreads();
        }
        for (int s = 0; s < 5; s++) {
            float nv[3]; int cnt = 0;
            for (int i = tid; i < NSTATE; i += bd) {
                int R = i / 36, Cc = i % 36;
                float acc = 0.f;
                #pragma unroll 6
                for (int k = 0; k < 36; k++) acc += T[R * 36 + k] * T[k * 36 + Cc];
                nv[cnt++] = acc;
            }
            __syncthreads();
            cnt = 0;
            for (int i = tid; i < NSTATE; i += bd) T[i] = nv[cnt++];
            __syncthreads();
        }
        // pack block-diagonal (column-major within block)
        for (int i = tid; i < 164; i += bd) {
            float val = 0.f;
            #pragma unroll
            for (int n = 0; n < 11; n++) {
                int off = OFFT(n);
                int sb = (n < 6) ? (n + 1) : (11 - n);
                int am = (n < 6) ? 0 : (n - 5);
                int d = i - off;
                if (d >= 0 && d < sb * sb) {
                    int aiI = d / sb, ao = d % sb;
                    val = T[(5 * (am + ao) + n) * 36 + (5 * (am + aiI) + n)];
                }
            }
            g_BSp[b][i] = val;
        }
    } else {
        // sixteen 6x6 expms (lockstep) + fold diagonal phases
        bool act = tid < 576;
        int mid = tid / 36, e = tid % 36, r = e / 6, c = e % 6;
        if (act) {
            int l = (mid % 8) / 4, m = mid % 4;
            float theta, g = 0.f;
            if (mid < 8) {  // squeeze
                theta = sq_r[l * 4 + m];
                if (c == r + 2)      g =  0.5f * sqrtf((float)((r + 1) * (r + 2)));
                else if (r == c + 2) g = -0.5f * sqrtf((float)((c + 1) * (c + 2)));
            } else {        // displacement
                theta = disp[l * 4 + m];
                if (r == c + 1)      g =  sqrtf((float)(c + 1));
                else if (c == r + 1) g = -sqrtf((float)(r + 1));
            }
            float a = theta * g * (1.f / 32.f);
            A[tid] = a; P[tid] = a; T[tid] = a + (r == c ? 1.f : 0.f);
        }
        __syncthreads();
        for (int j = 2; j <= 10; j++) {
            float nv = 0.f;
            if (act) {
                float s = 0.f;
                #pragma unroll
                for (int k = 0; k < 6; k++) s += P[mid * 36 + r * 6 + k] * A[mid * 36 + k * 6 + c];
                nv = s / (float)j;
            }
            __syncthreads();
            if (act) { P[tid] = nv; T[tid] += nv; }
            __syncthreads();
        }
        for (int s = 0; s < 5; s++) {
            float nv = 0.f;
            if (act) {
                float acc = 0.f;
                #pragma unroll
                for (int k = 0; k < 6; k++) acc += T[mid * 36 + r * 6 + k] * T[mid * 36 + k * 6 + c];
                nv = acc;
            }
            __syncthreads();
            if (act) T[tid] = nv;
            __syncthreads();
        }
        if (act) {
            int l = (mid % 8) / 4, m = mid % 4;
            float ang, sn, cs;
            if (mid < 8) {  // SQc = SQ @ diag(e^{i rot1 c})
                ang = rot1[l * 4 + m] * (float)c;
                sincosf(ang, &sn, &cs);
                g_U1c[l][0][m][e] = make_float2(T[tid] * cs, T[tid] * sn);
            } else {        // DPc = diag(e^{i kerr r^2}) @ DP @ diag(e^{i rot2 c})
                ang = kerr[l * 4 + m] * (float)(r * r) + rot2[l * 4 + m] * (float)c;
                sincosf(ang, &sn, &cs);
                g_U1c[l][1][m][e] = make_float2(T[tid] * cs, T[tid] * sn);
            }
        }
    }
}

// =======================================================================
// Main kernel: NS states per CTA, one thread per fiber (in-place gates).
// Padded state layout PL(i)=i+i/36.
// =======================================================================

// block-diagonal 36x36 BS gate on one fiber, in-place.
// S = state stride of the pair index R (36, 6 or 1).
template<int S>
__device__ __forceinline__ void apply2_blk(const float* __restrict__ pk,
                                           float2* __restrict__ st, int j)
{
    int baseP;
    if (S == 36)     baseP = j;                           // fiber = low 36 block
    else if (S == 6) baseP = (j / 6) * 222 + (j % 6);
    else             baseP = j * 37;                      // fiber = high block

    #pragma unroll
    for (int n = 0; n < 11; n++) {
        const int sb = (n < 6) ? (n + 1) : (11 - n);
        const int am = (n < 6) ? 0 : (n - 5);
        const int off = OFFT(n);
        float u[36];
        #pragma unroll
        for (int q = 0; q < (sb * sb + 3) / 4; q++) {
            float4 v = *(const float4*)(pk + off + 4 * q);
            u[4*q+0] = v.x; u[4*q+1] = v.y; u[4*q+2] = v.z; u[4*q+3] = v.w;
        }
        float2 x[6];
        #pragma unroll
        for (int a = 0; a < sb; a++) {
            const int R = 5 * (am + a) + n;
            const int o = (S == 36) ? R * 37 : (S == 6) ? (R * 6 + R / 6) : R;
            x[a] = st[baseP + o];
        }
        #pragma unroll
        for (int ao = 0; ao < sb; ao++) {
            float ar = 0.f, ai = 0.f;
            #pragma unroll
            for (int aiI = 0; aiI < sb; aiI++) {
                float uv = u[aiI * sb + ao];
                ar = fmaf(uv, x[aiI].x, ar);
                ai = fmaf(uv, x[aiI].y, ai);
            }
            const int R = 5 * (am + ao) + n;
            const int o = (S == 36) ? R * 37 : (S == 6) ? (R * 6 + R / 6) : R;
            st[baseP + o] = make_float2(ar, ai);
        }
    }
}

// complex 6x6 single-mode gate, 6 fibers per thread, in-place.
// PAR=true prunes checkerboard zeros (squeeze parity structure).
template<int m, bool PAR>
__device__ __forceinline__ void apply1c_mode(const float2* __restrict__ Uc,
                                             float2* __restrict__ st, int j)
{
    float2 u[36];
    #pragma unroll
    for (int q = 0; q < 18; q++) {
        float4 v = *(const float4*)((const float*)Uc + 4 * q);
        u[2*q]   = make_float2(v.x, v.y);
        u[2*q+1] = make_float2(v.z, v.w);
    }
    const int KS = (m == 0) ? 222 : (m == 1) ? 37 : (m == 2) ? 6 : 1;
    #pragma unroll
    for (int q = 0; q < 6; q++) {
        int A0;
        if (m == 0)      A0 = q * 37 + j;
        else if (m == 1) A0 = q * 222 + j;
        else if (m == 2) A0 = (q * 6 + j / 6) * 37 + (j % 6);
        else             A0 = q * 222 + j * 6 + j / 6;
        float2 x[6];
        #pragma unroll
        for (int k = 0; k < 6; k++) x[k] = st[A0 + k * KS];
        #pragma unroll
        for (int r = 0; r < 6; r++) {
            float ar = 0.f, ai = 0.f;
            #pragma unroll
            for (int k = 0; k < 6; k++) {
                if (PAR && (((r + k) & 1) != 0)) continue;
                float2 uv = u[r * 6 + k];
                ar = fmaf(uv.x, x[k].x, ar); ar = fmaf(-uv.y, x[k].y, ar);
                ai = fmaf(uv.x, x[k].y, ai); ai = fmaf( uv.y, x[k].x, ai);
            }
            st[A0 + r * KS] = make_float2(ar, ai);
        }
    }
}

extern __shared__ __align__(16) float2 sSt[];   // [NS][SPAD]

__global__ __launch_bounds__(TPB, 4) void qnn_kernel(const float* __restrict__ patches,
                                                     const float* __restrict__ enc_w,
                                                     const float* __restrict__ enc_b,
                                                     const float* __restrict__ ro_w,
                                                     const float* __restrict__ ro_b,
                                                     float* __restrict__ out)
{
    __shared__ __align__(16) float  sPk[2][164];
    __shared__ __align__(16) float2 sU1c[576];
    __shared__ float sAlpha[NS][4];
    __shared__ float sD0[NS][4][6];
    __shared__ float sPart[16][36];
    __shared__ float sQ[NS][4];

    int tid = threadIdx.x;
    int p0 = blockIdx.x * NS;
    int s = tid / 36, j = tid % 36;
    bool act = tid < NACT;
    float2* stS = sSt + s * SPAD;

    // stage gate 0 + all folded 6x6 gates
    for (int i = tid; i < 41; i += TPB)
        ((float4*)sPk[0])[i] = ((const float4*)g_BSp[0])[i];
    for (int i = tid; i < 288; i += TPB)
        ((float4*)sU1c)[i] = ((const float4*)g_U1c)[i];

    // alpha[s][m] = patches_row . enc_w^T + enc_b  (warp per task)
    {
        int w = tid >> 5, lane = tid & 31;
        for (int t = w; t < 16; t += 5) {
            int ss = t >> 2, m = t & 3;
            const float* pr = patches + (size_t)(p0 + ss) * 64;
            float v = pr[lane] * enc_w[m * 64 + lane]
                    + pr[lane + 32] * enc_w[m * 64 + lane + 32];
            #pragma unroll
            for (int o = 16; o; o >>= 1) v += __shfl_xor_sync(0xffffffffu, v, o);
            if (lane == 0) sAlpha[ss][m] = v + enc_b[m];
        }
    }
    __syncthreads();

    // Denc vacuum column: expm(alpha*(ad-a)) e0 via 28-term Taylor (exact
    // expm of the TRUNCATED generator, matching the reference eigh route)
    if (tid < 16) {
        int ss = tid >> 2, m = tid & 3;
        float al = sAlpha[ss][m];
        const float S1 = 1.f, S2 = 1.41421356f, S3 = 1.73205081f,
                    S4 = 2.f, S5 = 2.23606798f;
        float v0=1,v1=0,v2=0,v3=0,v4=0,v5=0;
        float t0=1,t1=0,t2=0,t3=0,t4=0,t5=0;
        for (int k = 1; k <= 28; k++) {
            float ik = al / (float)k;
            float n0 = ik * (          - S1 * t1);
            float n1 = ik * (S1 * t0 - S2 * t2);
            float n2 = ik * (S2 * t1 - S3 * t3);
            float n3 = ik * (S3 * t2 - S4 * t4);
            float n4 = ik * (S4 * t3 - S5 * t5);
            float n5 = ik * (S5 * t4);
            t0=n0; t1=n1; t2=n2; t3=n3; t4=n4; t5=n5;
            v0+=n0; v1+=n1; v2+=n2; v3+=n3; v4+=n4; v5+=n5;
        }
        sD0[ss][m][0]=v0; sD0[ss][m][1]=v1; sD0[ss][m][2]=v2;
        sD0[ss][m][3]=v3; sD0[ss][m][4]=v4; sD0[ss][m][5]=v5;
    }
    __syncthreads();

    // init state = outer product (real)
    if (act) {
        float a01 = sD0[s][0][j / 6] * sD0[s][1][j % 6];
        #pragma unroll
        for (int k = 0; k < 36; k++)
            stS[37 * j + k] = make_float2(a01 * sD0[s][2][k / 6] * sD0[s][3][k % 6], 0.f);
    }

    #define GATE2(K, SS)                                                          \
        __syncthreads();                                                          \
        if ((K) < 11)                                                             \
            for (int i = tid; i < 41; i += TPB)                                   \
                ((float4*)sPk[((K)+1) & 1])[i] = ((const float4*)g_BSp[(K)+1])[i];\
        if (act) apply2_blk<SS>(sPk[(K) & 1], stS, j);

    #define A1C(PTR, PAR)                                             \
        __syncthreads(); if (act) apply1c_mode<0, PAR>((PTR), stS, j);      \
        __syncthreads(); if (act) apply1c_mode<1, PAR>((PTR) + 36, stS, j); \
        __syncthreads(); if (act) apply1c_mode<2, PAR>((PTR) + 72, stS, j); \
        __syncthreads(); if (act) apply1c_mode<3, PAR>((PTR) + 108, stS, j);

    GATE2(0, 36) GATE2(1, 6) GATE2(2, 1)
    A1C(sU1c + 0,   true)      // layer 0 squeeze (rot1 folded; parity-sparse)
    GATE2(3, 36) GATE2(4, 6) GATE2(5, 1)
    A1C(sU1c + 144, false)     // layer 0 displacement (rot2+kerr folded)
    GATE2(6, 36) GATE2(7, 6) GATE2(8, 1)
    A1C(sU1c + 288, true)      // layer 1 squeeze
    GATE2(9, 36) GATE2(10, 6) GATE2(11, 1)
    A1C(sU1c + 432, false)     // layer 1 displacement

    // quadrature expectations
    __syncthreads();
    if (act) {
        const float W0 = 2.f, W1 = 2.82842712f, W2 = 3.46410162f,
                    W3 = 4.f, W4 = 4.47213595f;
        const float W[5] = {W0, W1, W2, W3, W4};
        int n0 = j / 6, n1 = j % 6;
        float q0 = 0.f, q1 = 0.f, q2 = 0.f, q3 = 0.f;
        #pragma unroll
        for (int k = 0; k < 36; k++) {
            int base = 37 * j + k;
            float2 s0 = stS[base];
            if (n0 < 5)    { float2 sN = stS[base + 222]; q0 += s0.x * sN.x + s0.y * sN.y; }
            if (n1 < 5)    { float2 sN = stS[base + 37];  q1 += s0.x * sN.x + s0.y * sN.y; }
            if (k / 6 < 5) { float2 sN = stS[base + 6];   q2 += W[k / 6] * (s0.x * sN.x + s0.y * sN.y); }
            if (k % 6 < 5) { float2 sN = stS[base + 1];   q3 += W[k % 6] * (s0.x * sN.x + s0.y * sN.y); }
        }
        if (n0 < 5) q0 *= W[n0];
        if (n1 < 5) q1 *= W[n1];
        sPart[s * 4 + 0][j] = q0; sPart[s * 4 + 1][j] = q1;
        sPart[s * 4 + 2][j] = q2; sPart[s * 4 + 3][j] = q3;
    }
    __syncthreads();
    if (tid < 16) {
        float acc = 0.f;
        #pragma unroll 6
        for (int k = 0; k < 36; k++) acc += sPart[tid][k];
        sQ[tid >> 2][tid & 3] = acc;
    }
    __syncthreads();

    // readout
    for (int idx = tid; idx < NS * DD; idx += TPB) {
        int ss = idx >> 6, d = idx & 63;
        float o = ro_b[d];
        #pragma unroll
        for (int m = 0; m < 4; m++) o = fmaf(sQ[ss][m], ro_w[d * 4 + m], o);
        out[(size_t)(p0 + ss) * DD + d] = o;
    }
}

// =======================================================================
extern "C" void kernel_launch(void* const* d_in, const int* in_sizes, int n_in,
                              void* d_out, int out_size)
{
    const float* patches = (const float*)d_in[0];
    const float* enc_w   = (const float*)d_in[1];
    const float* enc_b   = (const float*)d_in[2];
    const float* bs1     = (const float*)d_in[3];
    const float* rot1    = (const float*)d_in[4];
    const float* sq_r    = (const float*)d_in[5];
    const float* bs2     = (const float*)d_in[6];
    const float* rot2    = (const float*)d_in[7];
    const float* disp    = (const float*)d_in[8];
    const float* kerr    = (const float*)d_in[9];
    const float* ro_w    = (const float*)d_in[10];
    const float* ro_b    = (const float*)d_in[11];

    cudaFuncSetAttribute(qnn_kernel, cudaFuncAttributeMaxDynamicSharedMemorySize,
                         NS * SPAD * (int)sizeof(float2));
    precompute_kernel<<<13, 640>>>(bs1, sq_r, bs2, disp, rot1, rot2, kerr);
    qnn_kernel<<<PTOT / NS, TPB, NS * SPAD * sizeof(float2)>>>(
        patches, enc_w, enc_b, ro_w, ro_b, (float*)d_out);
}

// round 6
// speedup vs baseline: 2.0443x; 1.0162x over previous
#include <cuda_runtime.h>

#define MM 4
#define LL 2
#define NSTATE 1296       // 6^4
#define SPAD 1332         // padded: 36 blocks of 37 float2
#define PTOT 2048
#define DD 64
#define NS 2              // states per CTA
#define TPB 144           // 72 threads per state
#define TPS 72

// packed block-diagonal BS gates: blocks n=0..10, sizes 1..6..1, padded to 4 floats
__device__ __align__(16) float  g_BSp[12][164];
__device__ __align__(16) float2 g_U1c[LL][2][MM][36];  // folded complex 6x6 (SQ/DP)

__host__ __device__ __forceinline__ constexpr int OFFT(int n) {
    return n==0?0 : n==1?4 : n==2?8 : n==3?20 : n==4?36 : n==5?64
         : n==6?100 : n==7?128 : n==8?144 : n==9?156 : 160;
}

// =======================================================================
// Precompute: dense 36x36 expm per BS gate -> packed block-diagonal;
// sixteen 6x6 expms with rot/kerr phases folded (complex).
// =======================================================================
__global__ void precompute_kernel(const float* __restrict__ bs1,
                                  const float* __restrict__ sq_r,
                                  const float* __restrict__ bs2,
                                  const float* __restrict__ disp,
                                  const float* __restrict__ rot1,
                                  const float* __restrict__ rot2,
                                  const float* __restrict__ kerr)
{
    __shared__ float A[NSTATE], P[NSTATE], T[NSTATE];
    int tid = threadIdx.x, bd = blockDim.x;
    int b = blockIdx.x;

    if (b < 12) {
        int l = b / 6, half = (b % 6) / 3, m = b % 3;
        float theta = (half ? bs2 : bs1)[l * 3 + m];
        for (int i = tid; i < NSTATE; i += bd) {
            int R = i / 36, Cc = i % 36;
            int i1 = R / 6, i2 = R % 6, j1 = Cc / 6, j2 = Cc % 6;
            float g = 0.f;
            if (i1 == j1 + 1 && j2 == i2 + 1) g += sqrtf((float)((j1 + 1) * (i2 + 1)));
            if (j1 == i1 + 1 && i2 == j2 + 1) g -= sqrtf((float)((i1 + 1) * (j2 + 1)));
            float a = theta * g * (1.f / 32.f);
            A[i] = a; P[i] = a; T[i] = a + (R == Cc ? 1.f : 0.f);
        }
        __syncthreads();
        for (int j = 2; j <= 10; j++) {
            float inv = 1.f / (float)j;
            float nv[3]; int cnt = 0;
            for (int i = tid; i < NSTATE; i += bd) {
                int R = i / 36, Cc = i % 36;
                float s = 0.f;
                #pragma unroll 6
                for (int k = 0; k < 36; k++) s += P[R * 36 + k] * A[k * 36 + Cc];
                nv[cnt++] = s * inv;
            }
            __syncthreads();
            cnt = 0;
            for (int i = tid; i < NSTATE; i += bd) { P[i] = nv[cnt]; T[i] += nv[cnt]; cnt++; }
            __syncthreads();
        }
        for (int s = 0; s < 5; s++) {
            float nv[3]; int cnt = 0;
            for (int i = tid; i < NSTATE; i += bd) {
                int R = i / 36, Cc = i % 36;
                float acc = 0.f;
                #pragma unroll 6
                for (int k = 0; k < 36; k++) acc += T[R * 36 + k] * T[k * 36 + Cc];
                nv[cnt++] = acc;
            }
            __syncthreads();
            cnt = 0;
            for (int i = tid; i < NSTATE; i += bd) T[i] = nv[cnt++];
            __syncthreads();
        }
        for (int i = tid; i < 164; i += bd) {
            float val = 0.f;
            #pragma unroll
            for (int n = 0; n < 11; n++) {
                int off = OFFT(n);
                int sb = (n < 6) ? (n + 1) : (11 - n);
                int am = (n < 6) ? 0 : (n - 5);
                int d = i - off;
                if (d >= 0 && d < sb * sb) {
                    int aiI = d / sb, ao = d % sb;
                    val = T[(5 * (am + ao) + n) * 36 + (5 * (am + aiI) + n)];
                }
            }
            g_BSp[b][i] = val;
        }
    } else {
        bool act = tid < 576;
        int mid = tid / 36, e = tid % 36, r = e / 6, c = e % 6;
        if (act) {
            int l = (mid % 8) / 4, m = mid % 4;
            float theta, g = 0.f;
            if (mid < 8) {  // squeeze
                theta = sq_r[l * 4 + m];
                if (c == r + 2)      g =  0.5f * sqrtf((float)((r + 1) * (r + 2)));
                else if (r == c + 2) g = -0.5f * sqrtf((float)((c + 1) * (c + 2)));
            } else {        // displacement
                theta = disp[l * 4 + m];
                if (r == c + 1)      g =  sqrtf((float)(c + 1));
                else if (c == r + 1) g = -sqrtf((float)(r + 1));
            }
            float a = theta * g * (1.f / 32.f);
            A[tid] = a; P[tid] = a; T[tid] = a + (r == c ? 1.f : 0.f);
        }
        __syncthreads();
        for (int j = 2; j <= 10; j++) {
            float nv = 0.f;
            if (act) {
                float s = 0.f;
                #pragma unroll
                for (int k = 0; k < 6; k++) s += P[mid * 36 + r * 6 + k] * A[mid * 36 + k * 6 + c];
                nv = s / (float)j;
            }
            __syncthreads();
            if (act) { P[tid] = nv; T[tid] += nv; }
            __syncthreads();
        }
        for (int s = 0; s < 5; s++) {
            float nv = 0.f;
            if (act) {
                float acc = 0.f;
                #pragma unroll
                for (int k = 0; k < 6; k++) acc += T[mid * 36 + r * 6 + k] * T[mid * 36 + k * 6 + c];
                nv = acc;
            }
            __syncthreads();
            if (act) T[tid] = nv;
            __syncthreads();
        }
        if (act) {
            int l = (mid % 8) / 4, m = mid % 4;
            float ang, sn, cs;
            if (mid < 8) {  // SQc = SQ @ diag(e^{i rot1 c})
                ang = rot1[l * 4 + m] * (float)c;
                sincosf(ang, &sn, &cs);
                g_U1c[l][0][m][e] = make_float2(T[tid] * cs, T[tid] * sn);
            } else {        // DPc = diag(e^{i kerr r^2}) @ DP @ diag(e^{i rot2 c})
                ang = kerr[l * 4 + m] * (float)(r * r) + rot2[l * 4 + m] * (float)c;
                sincosf(ang, &sn, &cs);
                g_U1c[l][1][m][e] = make_float2(T[tid] * cs, T[tid] * sn);
            }
        }
    }
}

// =======================================================================
// Main kernel: NS states per CTA, 72 threads/state.
// apply2: 2 threads per fiber, split by diagonal-block parity.
// =======================================================================

template<int S, int PAR>
__device__ __forceinline__ void apply2_blk(const float* __restrict__ pk,
                                           float2* __restrict__ st, int j)
{
    int baseP;
    if (S == 36)     baseP = j;
    else if (S == 6) baseP = (j / 6) * 222 + (j % 6);
    else             baseP = j * 37;

    #pragma unroll
    for (int n = PAR; n < 11; n += 2) {
        const int sb = (n < 6) ? (n + 1) : (11 - n);
        const int am = (n < 6) ? 0 : (n - 5);
        const int off = OFFT(n);
        float u[36];
        #pragma unroll
        for (int q = 0; q < (sb * sb + 3) / 4; q++) {
            float4 v = *(const float4*)(pk + off + 4 * q);
            u[4*q+0] = v.x; u[4*q+1] = v.y; u[4*q+2] = v.z; u[4*q+3] = v.w;
        }
        float2 x[6];
        #pragma unroll
        for (int a = 0; a < sb; a++) {
            const int R = 5 * (am + a) + n;
            const int o = (S == 36) ? R * 37 : (S == 6) ? (R * 6 + R / 6) : R;
            x[a] = st[baseP + o];
        }
        #pragma unroll
        for (int ao = 0; ao < sb; ao++) {
            float ar = 0.f, ai = 0.f;
            #pragma unroll
            for (int aiI = 0; aiI < sb; aiI++) {
                float uv = u[aiI * sb + ao];
                ar = fmaf(uv, x[aiI].x, ar);
                ai = fmaf(uv, x[aiI].y, ai);
            }
            const int R = 5 * (am + ao) + n;
            const int o = (S == 36) ? R * 37 : (S == 6) ? (R * 6 + R / 6) : R;
            st[baseP + o] = make_float2(ar, ai);
        }
    }
}

// complex 6x6 single-mode gate, 3 fibers per thread (72 threads/state), in-place
template<int m>
__device__ __forceinline__ void apply1c_mode(const float2* __restrict__ Uc,
                                             float2* __restrict__ st, int ft)
{
    const int KS = (m == 0) ? 222 : (m == 1) ? 37 : (m == 2) ? 6 : 1;
    int A0[3];
    float2 x[3][6];
    #pragma unroll
    for (int q = 0; q < 3; q++) {
        int f = ft + 72 * q;
        int a0;
        if (m == 0)      a0 = f + f / 36;
        else if (m == 1) a0 = (f / 36) * 222 + (f % 36);
        else if (m == 2) a0 = (f / 6) * 37 + (f % 6);
        else             a0 = (f / 6) * 37 + (f % 6) * 6;
        A0[q] = a0;
        #pragma unroll
        for (int k = 0; k < 6; k++) x[q][k] = st[a0 + k * KS];
    }
    #pragma unroll
    for (int r = 0; r < 6; r++) {
        float4 v0 = *(const float4*)((const float*)Uc + r * 12);
        float4 v1 = *(const float4*)((const float*)Uc + r * 12 + 4);
        float4 v2 = *(const float4*)((const float*)Uc + r * 12 + 8);
        float2 u[6];
        u[0] = make_float2(v0.x, v0.y); u[1] = make_float2(v0.z, v0.w);
        u[2] = make_float2(v1.x, v1.y); u[3] = make_float2(v1.z, v1.w);
        u[4] = make_float2(v2.x, v2.y); u[5] = make_float2(v2.z, v2.w);
        #pragma unroll
        for (int q = 0; q < 3; q++) {
            float ar = 0.f, ai = 0.f;
            #pragma unroll
            for (int k = 0; k < 6; k++) {
                ar = fmaf(u[k].x, x[q][k].x, ar); ar = fmaf(-u[k].y, x[q][k].y, ar);
                ai = fmaf(u[k].x, x[q][k].y, ai); ai = fmaf( u[k].y, x[q][k].x, ai);
            }
            st[A0[q] + r * KS] = make_float2(ar, ai);
        }
    }
}

extern __shared__ __align__(16) float2 sSt[];   // [NS][SPAD]

__global__ __launch_bounds__(TPB, 6) void qnn_kernel(const float* __restrict__ patches,
                                                     const float* __restrict__ enc_w,
                                                     const float* __restrict__ enc_b,
                                                     const float* __restrict__ ro_w,
                                                     const float* __restrict__ ro_b,
                                                     float* __restrict__ out)
{
    __shared__ __align__(16) float  sPk[2][164];
    __shared__ __align__(16) float2 sU1c[576];
    __shared__ float sAlpha[NS][4];
    __shared__ float sD0[NS][4][6];
    __shared__ float sPart[NS * 4][TPS];
    __shared__ float sQ[NS][4];

    int tid = threadIdx.x;
    int p0 = blockIdx.x * NS;
    // warp-uniform parity mapping: par = tid/72 (only 1 of 4.5 warps mixed)
    int par = tid / 72;
    int r72 = tid - par * 72;
    int s = r72 / 36, j = r72 - s * 36;
    int ft = j + par * 36;            // per-state thread index 0..71
    float2* stS = sSt + s * SPAD;

    // stage gate 0 + all folded 6x6 gates
    for (int i = tid; i < 41; i += TPB)
        ((float4*)sPk[0])[i] = __ldg((const float4*)g_BSp[0] + i);
    for (int i = tid; i < 288; i += TPB)
        ((float4*)sU1c)[i] = __ldg((const float4*)g_U1c + i);

    // alpha[s][m] = patches_row . enc_w^T + enc_b
    {
        int w = tid >> 5, lane = tid & 31;
        if (w < 4) {
            for (int task = w; task < 8; task += 4) {
                int ss = task >> 2, m = task & 3;
                const float* pr = patches + (size_t)(p0 + ss) * 64;
                float v = pr[lane] * enc_w[m * 64 + lane]
                        + pr[lane + 32] * enc_w[m * 64 + lane + 32];
                #pragma unroll
                for (int o = 16; o; o >>= 1) v += __shfl_xor_sync(0xffffffffu, v, o);
                if (lane == 0) sAlpha[ss][m] = v + enc_b[m];
            }
        }
    }
    __syncthreads();

    // Denc vacuum column: expm(alpha*(ad-a)) e0, 28-term Taylor (truncated gen)
    if (tid < 8) {
        int ss = tid >> 2, m = tid & 3;
        float al = sAlpha[ss][m];
        const float S1 = 1.f, S2 = 1.41421356f, S3 = 1.73205081f,
                    S4 = 2.f, S5 = 2.23606798f;
        float v0=1,v1=0,v2=0,v3=0,v4=0,v5=0;
        float t0=1,t1=0,t2=0,t3=0,t4=0,t5=0;
        for (int k = 1; k <= 28; k++) {
            float ik = al / (float)k;
            float n0 = ik * (          - S1 * t1);
            float n1 = ik * (S1 * t0 - S2 * t2);
            float n2 = ik * (S2 * t1 - S3 * t3);
            float n3 = ik * (S3 * t2 - S4 * t4);
            float n4 = ik * (S4 * t3 - S5 * t5);
            float n5 = ik * (S5 * t4);
            t0=n0; t1=n1; t2=n2; t3=n3; t4=n4; t5=n5;
            v0+=n0; v1+=n1; v2+=n2; v3+=n3; v4+=n4; v5+=n5;
        }
        sD0[ss][m][0]=v0; sD0[ss][m][1]=v1; sD0[ss][m][2]=v2;
        sD0[ss][m][3]=v3; sD0[ss][m][4]=v4; sD0[ss][m][5]=v5;
    }
    __syncthreads();

    // init state = outer product (real); each thread fills 18 elements
    {
        float a01 = sD0[s][0][j / 6] * sD0[s][1][j % 6];
        int k0 = par * 18;
        #pragma unroll
        for (int k = 0; k < 18; k++) {
            int kk = k0 + k;
            stS[37 * j + kk] =
                make_float2(a01 * sD0[s][2][kk / 6] * sD0[s][3][kk % 6], 0.f);
        }
    }

    #define GATE2(K, SS)                                                          \
        __syncthreads();                                                          \
        if ((K) < 11) {                                                           \
            for (int i = tid; i < 41; i += TPB)                                   \
                ((float4*)sPk[((K)+1)&1])[i] =                                    \
                    __ldg((const float4*)g_BSp[(K)+1] + i);                       \
        }                                                                         \
        if (par == 0) apply2_blk<SS,0>(sPk[(K)&1], stS, j);                       \
        else          apply2_blk<SS,1>(sPk[(K)&1], stS, j);

    for (int h = 0; h < 4; h++) {
        int kg = 3 * h;
        GATE2(kg, 36)
        GATE2(kg + 1, 6)
        GATE2(kg + 2, 1)
        const float2* P1 = sU1c + h * 144;   // h: SQ(l0), DP(l0), SQ(l1), DP(l1)
        __syncthreads(); apply1c_mode<0>(P1,       stS, ft);
        __syncthreads(); apply1c_mode<1>(P1 + 36,  stS, ft);
        __syncthreads(); apply1c_mode<2>(P1 + 72,  stS, ft);
        __syncthreads(); apply1c_mode<3>(P1 + 108, stS, ft);
    }

    // quadrature expectations
    __syncthreads();
    {
        const float W[5] = {2.f, 2.82842712f, 3.46410162f, 4.f, 4.47213595f};
        int n0 = j / 6, n1 = j % 6;
        float q0 = 0.f, q1 = 0.f, q2 = 0.f, q3 = 0.f;
        int k0 = par * 18;
        #pragma unroll
        for (int k = 0; k < 18; k++) {
            int kk = k0 + k;
            int base = 37 * j + kk;
            float2 s0 = stS[base];
            if (n0 < 5)     { float2 sN = stS[base + 222]; q0 += s0.x * sN.x + s0.y * sN.y; }
            if (n1 < 5)     { float2 sN = stS[base + 37];  q1 += s0.x * sN.x + s0.y * sN.y; }
            if (kk / 6 < 5) { float2 sN = stS[base + 6];   q2 += W[kk / 6] * (s0.x * sN.x + s0.y * sN.y); }
            if (kk % 6 < 5) { float2 sN = stS[base + 1];   q3 += W[kk % 6] * (s0.x * sN.x + s0.y * sN.y); }
        }
        if (n0 < 5) q0 *= W[n0];
        if (n1 < 5) q1 *= W[n1];
        sPart[s * 4 + 0][ft] = q0; sPart[s * 4 + 1][ft] = q1;
        sPart[s * 4 + 2][ft] = q2; sPart[s * 4 + 3][ft] = q3;
    }
    __syncthreads();
    if (tid < 8) {
        float acc = 0.f;
        #pragma unroll 8
        for (int k = 0; k < TPS; k++) acc += sPart[tid][k];
        sQ[tid >> 2][tid & 3] = acc;
    }
    __syncthreads();

    // readout
    if (tid < NS * DD) {
        int ss = tid >> 6, d = tid & 63;
        float o = ro_b[d];
        #pragma unroll
        for (int m = 0; m < 4; m++) o = fmaf(sQ[ss][m], ro_w[d * 4 + m], o);
        out[(size_t)(p0 + ss) * DD + d] = o;
    }
}

// =======================================================================
extern "C" void kernel_launch(void* const* d_in, const int* in_sizes, int n_in,
                              void* d_out, int out_size)
{
    const float* patches = (const float*)d_in[0];
    const float* enc_w   = (const float*)d_in[1];
    const float* enc_b   = (const float*)d_in[2];
    const float* bs1     = (const float*)d_in[3];
    const float* rot1    = (const float*)d_in[4];
    const float* sq_r    = (const float*)d_in[5];
    const float* bs2     = (const float*)d_in[6];
    const float* rot2    = (const float*)d_in[7];
    const float* disp    = (const float*)d_in[8];
    const float* kerr    = (const float*)d_in[9];
    const float* ro_w    = (const float*)d_in[10];
    const float* ro_b    = (const float*)d_in[11];

    precompute_kernel<<<13, 640>>>(bs1, sq_r, bs2, disp, rot1, rot2, kerr);
    qnn_kernel<<<PTOT / NS, TPB, NS * SPAD * sizeof(float2)>>>(
        patches, enc_w, enc_b, ro_w, ro_b, (float*)d_out);
}

// round 7
// speedup vs baseline: 2.2548x; 1.1030x over previous
#include <cuda_runtime.h>

#define MM 4
#define LL 2
#define NSTATE 1296       // 6^4
#define SPAD 1332         // padded: 36 blocks of 37 float2
#define PTOT 2048
#define DD 64
#define NS 2              // states per CTA
#define TPB 144           // 72 threads per state
#define TPS 72

// packed block-diagonal BS gates: blocks n=0..10, sizes 1..6..1, padded to 4 floats
__device__ __align__(16) float  g_BSp[12][164];
__device__ __align__(16) float2 g_U1c[LL][2][MM][36];  // folded complex 6x6 (SQ/DP)

__host__ __device__ __forceinline__ constexpr int OFFT(int n) {
    return n==0?0 : n==1?4 : n==2?8 : n==3?20 : n==4?36 : n==5?64
         : n==6?100 : n==7?128 : n==8?144 : n==9?156 : 160;
}

// =======================================================================
// Precompute (ONE block, one thread per small matrix):
//  - 132 threads: BS gate g, photon-number block n -> sb x sb expm (sb<=6),
//    embedded in a zero-padded 6x6 so all loops are compile-time.
//  - 16 threads: 6x6 SQ/DP expm with rot/kerr phases folded (complex out).
// expm via scaling (2^-5) + 10-term Taylor + 5 squarings (register resident).
// =======================================================================
__global__ void precompute_kernel(const float* __restrict__ bs1,
                                  const float* __restrict__ sq_r,
                                  const float* __restrict__ bs2,
                                  const float* __restrict__ disp,
                                  const float* __restrict__ rot1,
                                  const float* __restrict__ rot2,
                                  const float* __restrict__ kerr)
{
    int t = threadIdx.x;
    float A[6][6], P[6][6], T[6][6];

    if (t < 132) {
        // ---- BS gate g, block n ----
        int g = t / 11, n = t % 11;
        int l = g / 6, half = (g % 6) / 3, m = g % 3;
        float theta = (half ? bs2 : bs1)[l * 3 + m];
        const int sb = (n < 6) ? (n + 1) : (11 - n);
        const int am = (n < 6) ? 0 : (n - 5);
        #pragma unroll
        for (int r = 0; r < 6; r++) {
            #pragma unroll
            for (int c = 0; c < 6; c++) {
                float gg = 0.f;
                if (r < sb && c < sb) {
                    int R = 5 * (am + r) + n, Cc = 5 * (am + c) + n;
                    int i1 = R / 6, i2 = R % 6, j1 = Cc / 6, j2 = Cc % 6;
                    if (i1 == j1 + 1 && j2 == i2 + 1) gg += sqrtf((float)((j1 + 1) * (i2 + 1)));
                    if (j1 == i1 + 1 && i2 == j2 + 1) gg -= sqrtf((float)((i1 + 1) * (j2 + 1)));
                }
                float a = theta * gg * (1.f / 32.f);
                A[r][c] = a; P[r][c] = a; T[r][c] = a + (r == c ? 1.f : 0.f);
            }
        }
        for (int j = 2; j <= 10; j++) {
            float inv = 1.f / (float)j;
            float Pn[6][6];
            #pragma unroll
            for (int r = 0; r < 6; r++)
                #pragma unroll
                for (int c = 0; c < 6; c++) {
                    float s = 0.f;
                    #pragma unroll
                    for (int k = 0; k < 6; k++) s += P[r][k] * A[k][c];
                    Pn[r][c] = s * inv;
                }
            #pragma unroll
            for (int r = 0; r < 6; r++)
                #pragma unroll
                for (int c = 0; c < 6; c++) { P[r][c] = Pn[r][c]; T[r][c] += Pn[r][c]; }
        }
        for (int s = 0; s < 5; s++) {
            float Tn[6][6];
            #pragma unroll
            for (int r = 0; r < 6; r++)
                #pragma unroll
                for (int c = 0; c < 6; c++) {
                    float acc = 0.f;
                    #pragma unroll
                    for (int k = 0; k < 6; k++) acc += T[r][k] * T[k][c];
                    Tn[r][c] = acc;
                }
            #pragma unroll
            for (int r = 0; r < 6; r++)
                #pragma unroll
                for (int c = 0; c < 6; c++) T[r][c] = Tn[r][c];
        }
        // pack column-major within block: packed[ci*sb + ro] = U[ro][ci]
        int off = OFFT(n);
        #pragma unroll
        for (int ro = 0; ro < 6; ro++)
            #pragma unroll
            for (int ci = 0; ci < 6; ci++)
                if (ro < sb && ci < sb)
                    g_BSp[g][off + ci * sb + ro] = T[ro][ci];
    } else if (t < 148) {
        // ---- SQ (mid<8) / DP 6x6 expm + phase folding ----
        int mid = t - 132;
        int l = (mid % 8) / 4, m = mid % 4;
        float theta;
        if (mid < 8) theta = sq_r[l * 4 + m];
        else         theta = disp[l * 4 + m];
        #pragma unroll
        for (int r = 0; r < 6; r++) {
            #pragma unroll
            for (int c = 0; c < 6; c++) {
                float gg = 0.f;
                if (mid < 8) {
                    if (c == r + 2)      gg =  0.5f * sqrtf((float)((r + 1) * (r + 2)));
                    else if (r == c + 2) gg = -0.5f * sqrtf((float)((c + 1) * (c + 2)));
                } else {
                    if (r == c + 1)      gg =  sqrtf((float)(c + 1));
                    else if (c == r + 1) gg = -sqrtf((float)(r + 1));
                }
                float a = theta * gg * (1.f / 32.f);
                A[r][c] = a; P[r][c] = a; T[r][c] = a + (r == c ? 1.f : 0.f);
            }
        }
        for (int j = 2; j <= 10; j++) {
            float inv = 1.f / (float)j;
            float Pn[6][6];
            #pragma unroll
            for (int r = 0; r < 6; r++)
                #pragma unroll
                for (int c = 0; c < 6; c++) {
                    float s = 0.f;
                    #pragma unroll
                    for (int k = 0; k < 6; k++) s += P[r][k] * A[k][c];
                    Pn[r][c] = s * inv;
                }
            #pragma unroll
            for (int r = 0; r < 6; r++)
                #pragma unroll
                for (int c = 0; c < 6; c++) { P[r][c] = Pn[r][c]; T[r][c] += Pn[r][c]; }
        }
        for (int s = 0; s < 5; s++) {
            float Tn[6][6];
            #pragma unroll
            for (int r = 0; r < 6; r++)
                #pragma unroll
                for (int c = 0; c < 6; c++) {
                    float acc = 0.f;
                    #pragma unroll
                    for (int k = 0; k < 6; k++) acc += T[r][k] * T[k][c];
                    Tn[r][c] = acc;
                }
            #pragma unroll
            for (int r = 0; r < 6; r++)
                #pragma unroll
                for (int c = 0; c < 6; c++) T[r][c] = Tn[r][c];
        }
        #pragma unroll
        for (int r = 0; r < 6; r++) {
            #pragma unroll
            for (int c = 0; c < 6; c++) {
                float ang, sn, cs;
                if (mid < 8) {   // SQc = SQ @ diag(e^{i rot1 c})
                    ang = rot1[l * 4 + m] * (float)c;
                    sincosf(ang, &sn, &cs);
                    g_U1c[l][0][m][r * 6 + c] = make_float2(T[r][c] * cs, T[r][c] * sn);
                } else {         // DPc = diag(e^{i kerr r^2}) @ DP @ diag(e^{i rot2 c})
                    ang = kerr[l * 4 + m] * (float)(r * r) + rot2[l * 4 + m] * (float)c;
                    sincosf(ang, &sn, &cs);
                    g_U1c[l][1][m][r * 6 + c] = make_float2(T[r][c] * cs, T[r][c] * sn);
                }
            }
        }
    }
}

// =======================================================================
// Main kernel: NS states per CTA, 72 threads/state.
// apply2: 2 threads per fiber, split by diagonal-block parity.
// =======================================================================

template<int S, int PAR>
__device__ __forceinline__ void apply2_blk(const float* __restrict__ pk,
                                           float2* __restrict__ st, int j)
{
    int baseP;
    if (S == 36)     baseP = j;
    else if (S == 6) baseP = (j / 6) * 222 + (j % 6);
    else             baseP = j * 37;

    #pragma unroll
    for (int n = PAR; n < 11; n += 2) {
        const int sb = (n < 6) ? (n + 1) : (11 - n);
        const int am = (n < 6) ? 0 : (n - 5);
        const int off = OFFT(n);
        float u[36];
        #pragma unroll
        for (int q = 0; q < (sb * sb + 3) / 4; q++) {
            float4 v = *(const float4*)(pk + off + 4 * q);
            u[4*q+0] = v.x; u[4*q+1] = v.y; u[4*q+2] = v.z; u[4*q+3] = v.w;
        }
        float2 x[6];
        #pragma unroll
        for (int a = 0; a < sb; a++) {
            const int R = 5 * (am + a) + n;
            const int o = (S == 36) ? R * 37 : (S == 6) ? (R * 6 + R / 6) : R;
            x[a] = st[baseP + o];
        }
        #pragma unroll
        for (int ao = 0; ao < sb; ao++) {
            float ar = 0.f, ai = 0.f;
            #pragma unroll
            for (int aiI = 0; aiI < sb; aiI++) {
                float uv = u[aiI * sb + ao];
                ar = fmaf(uv, x[aiI].x, ar);
                ai = fmaf(uv, x[aiI].y, ai);
            }
            const int R = 5 * (am + ao) + n;
            const int o = (S == 36) ? R * 37 : (S == 6) ? (R * 6 + R / 6) : R;
            st[baseP + o] = make_float2(ar, ai);
        }
    }
}

// complex 6x6 single-mode gate, 3 fibers per thread (72 threads/state), in-place
template<int m>
__device__ __forceinline__ void apply1c_mode(const float2* __restrict__ Uc,
                                             float2* __restrict__ st, int ft)
{
    const int KS = (m == 0) ? 222 : (m == 1) ? 37 : (m == 2) ? 6 : 1;
    int A0[3];
    float2 x[3][6];
    #pragma unroll
    for (int q = 0; q < 3; q++) {
        int f = ft + 72 * q;
        int a0;
        if (m == 0)      a0 = f + f / 36;
        else if (m == 1) a0 = (f / 36) * 222 + (f % 36);
        else if (m == 2) a0 = (f / 6) * 37 + (f % 6);
        else             a0 = (f / 6) * 37 + (f % 6) * 6;
        A0[q] = a0;
        #pragma unroll
        for (int k = 0; k < 6; k++) x[q][k] = st[a0 + k * KS];
    }
    #pragma unroll
    for (int r = 0; r < 6; r++) {
        float4 v0 = *(const float4*)((const float*)Uc + r * 12);
        float4 v1 = *(const float4*)((const float*)Uc + r * 12 + 4);
        float4 v2 = *(const float4*)((const float*)Uc + r * 12 + 8);
        float2 u[6];
        u[0] = make_float2(v0.x, v0.y); u[1] = make_float2(v0.z, v0.w);
        u[2] = make_float2(v1.x, v1.y); u[3] = make_float2(v1.z, v1.w);
        u[4] = make_float2(v2.x, v2.y); u[5] = make_float2(v2.z, v2.w);
        #pragma unroll
        for (int q = 0; q < 3; q++) {
            float ar = 0.f, ai = 0.f;
            #pragma unroll
            for (int k = 0; k < 6; k++) {
                ar = fmaf(u[k].x, x[q][k].x, ar); ar = fmaf(-u[k].y, x[q][k].y, ar);
                ai = fmaf(u[k].x, x[q][k].y, ai); ai = fmaf( u[k].y, x[q][k].x, ai);
            }
            st[A0[q] + r * KS] = make_float2(ar, ai);
        }
    }
}

extern __shared__ __align__(16) float2 sSt[];   // [NS][SPAD]

__global__ __launch_bounds__(TPB, 7) void qnn_kernel(const float* __restrict__ patches,
                                                     const float* __restrict__ enc_w,
                                                     const float* __restrict__ enc_b,
                                                     const float* __restrict__ ro_w,
                                                     const float* __restrict__ ro_b,
                                                     float* __restrict__ out)
{
    __shared__ __align__(16) float  sPk[2][164];
    __shared__ __align__(16) float2 sU1c[576];
    __shared__ float sAlpha[NS][4];
    __shared__ float sD0[NS][4][6];
    __shared__ float sPart[NS * 4][TPS];
    __shared__ float sQ[NS][4];

    int tid = threadIdx.x;
    int p0 = blockIdx.x * NS;
    // warp-uniform parity mapping: par = tid/72 (only 1 of 4.5 warps mixed)
    int par = tid / 72;
    int r72 = tid - par * 72;
    int s = r72 / 36, j = r72 - s * 36;
    int ft = j + par * 36;            // per-state thread index 0..71
    float2* stS = sSt + s * SPAD;

    // stage gate 0 + all folded 6x6 gates
    for (int i = tid; i < 41; i += TPB)
        ((float4*)sPk[0])[i] = __ldg((const float4*)g_BSp[0] + i);
    for (int i = tid; i < 288; i += TPB)
        ((float4*)sU1c)[i] = __ldg((const float4*)g_U1c + i);

    // alpha[s][m] = patches_row . enc_w^T + enc_b
    {
        int w = tid >> 5, lane = tid & 31;
        if (w < 4) {
            for (int task = w; task < 8; task += 4) {
                int ss = task >> 2, m = task & 3;
                const float* pr = patches + (size_t)(p0 + ss) * 64;
                float v = pr[lane] * enc_w[m * 64 + lane]
                        + pr[lane + 32] * enc_w[m * 64 + lane + 32];
                #pragma unroll
                for (int o = 16; o; o >>= 1) v += __shfl_xor_sync(0xffffffffu, v, o);
                if (lane == 0) sAlpha[ss][m] = v + enc_b[m];
            }
        }
    }
    __syncthreads();

    // Denc vacuum column: expm(alpha*(ad-a)) e0, 28-term Taylor (truncated gen)
    if (tid < 8) {
        int ss = tid >> 2, m = tid & 3;
        float al = sAlpha[ss][m];
        const float S1 = 1.f, S2 = 1.41421356f, S3 = 1.73205081f,
                    S4 = 2.f, S5 = 2.23606798f;
        float v0=1,v1=0,v2=0,v3=0,v4=0,v5=0;
        float t0=1,t1=0,t2=0,t3=0,t4=0,t5=0;
        for (int k = 1; k <= 28; k++) {
            float ik = al / (float)k;
            float n0 = ik * (          - S1 * t1);
            float n1 = ik * (S1 * t0 - S2 * t2);
            float n2 = ik * (S2 * t1 - S3 * t3);
            float n3 = ik * (S3 * t2 - S4 * t4);
            float n4 = ik * (S4 * t3 - S5 * t5);
            float n5 = ik * (S5 * t4);
            t0=n0; t1=n1; t2=n2; t3=n3; t4=n4; t5=n5;
            v0+=n0; v1+=n1; v2+=n2; v3+=n3; v4+=n4; v5+=n5;
        }
        sD0[ss][m][0]=v0; sD0[ss][m][1]=v1; sD0[ss][m][2]=v2;
        sD0[ss][m][3]=v3; sD0[ss][m][4]=v4; sD0[ss][m][5]=v5;
    }
    __syncthreads();

    // init state = outer product (real); each thread fills 18 elements
    {
        float a01 = sD0[s][0][j / 6] * sD0[s][1][j % 6];
        int k0 = par * 18;
        #pragma unroll
        for (int k = 0; k < 18; k++) {
            int kk = k0 + k;
            stS[37 * j + kk] =
                make_float2(a01 * sD0[s][2][kk / 6] * sD0[s][3][kk % 6], 0.f);
        }
    }

    #define GATE2(K, SS)                                                          \
        __syncthreads();                                                          \
        if ((K) < 11) {                                                           \
            for (int i = tid; i < 41; i += TPB)                                   \
                ((float4*)sPk[((K)+1)&1])[i] =                                    \
                    __ldg((const float4*)g_BSp[(K)+1] + i);                       \
        }                                                                         \
        if (par == 0) apply2_blk<SS,0>(sPk[(K)&1], stS, j);                       \
        else          apply2_blk<SS,1>(sPk[(K)&1], stS, j);

    for (int h = 0; h < 4; h++) {
        int kg = 3 * h;
        GATE2(kg, 36)
        GATE2(kg + 1, 6)
        GATE2(kg + 2, 1)
        const float2* P1 = sU1c + h * 144;   // h: SQ(l0), DP(l0), SQ(l1), DP(l1)
        __syncthreads(); apply1c_mode<0>(P1,       stS, ft);
        __syncthreads(); apply1c_mode<1>(P1 + 36,  stS, ft);
        __syncthreads(); apply1c_mode<2>(P1 + 72,  stS, ft);
        __syncthreads(); apply1c_mode<3>(P1 + 108, stS, ft);
    }

    // quadrature expectations
    __syncthreads();
    {
        const float W[5] = {2.f, 2.82842712f, 3.46410162f, 4.f, 4.47213595f};
        int n0 = j / 6, n1 = j % 6;
        float q0 = 0.f, q1 = 0.f, q2 = 0.f, q3 = 0.f;
        int k0 = par * 18;
        #pragma unroll
        for (int k = 0; k < 18; k++) {
            int kk = k0 + k;
            int base = 37 * j + kk;
            float2 s0 = stS[base];
            if (n0 < 5)     { float2 sN = stS[base + 222]; q0 += s0.x * sN.x + s0.y * sN.y; }
            if (n1 < 5)     { float2 sN = stS[base + 37];  q1 += s0.x * sN.x + s0.y * sN.y; }
            if (kk / 6 < 5) { float2 sN = stS[base + 6];   q2 += W[kk / 6] * (s0.x * sN.x + s0.y * sN.y); }
            if (kk % 6 < 5) { float2 sN = stS[base + 1];   q3 += W[kk % 6] * (s0.x * sN.x + s0.y * sN.y); }
        }
        if (n0 < 5) q0 *= W[n0];
        if (n1 < 5) q1 *= W[n1];
        sPart[s * 4 + 0][ft] = q0; sPart[s * 4 + 1][ft] = q1;
        sPart[s * 4 + 2][ft] = q2; sPart[s * 4 + 3][ft] = q3;
    }
    __syncthreads();
    if (tid < 8) {
        float acc = 0.f;
        #pragma unroll 8
        for (int k = 0; k < TPS; k++) acc += sPart[tid][k];
        sQ[tid >> 2][tid & 3] = acc;
    }
    __syncthreads();

    // readout
    if (tid < NS * DD) {
        int ss = tid >> 6, d = tid & 63;
        float o = ro_b[d];
        #pragma unroll
        for (int m = 0; m < 4; m++) o = fmaf(sQ[ss][m], ro_w[d * 4 + m], o);
        out[(size_t)(p0 + ss) * DD + d] = o;
    }
}

// =======================================================================
extern "C" void kernel_launch(void* const* d_in, const int* in_sizes, int n_in,
                              void* d_out, int out_size)
{
    const float* patches = (const float*)d_in[0];
    const float* enc_w   = (const float*)d_in[1];
    const float* enc_b   = (const float*)d_in[2];
    const float* bs1     = (const float*)d_in[3];
    const float* rot1    = (const float*)d_in[4];
    const float* sq_r    = (const float*)d_in[5];
    const float* bs2     = (const float*)d_in[6];
    const float* rot2    = (const float*)d_in[7];
    const float* disp    = (const float*)d_in[8];
    const float* kerr    = (const float*)d_in[9];
    const float* ro_w    = (const float*)d_in[10];
    const float* ro_b    = (const float*)d_in[11];

    precompute_kernel<<<1, 148>>>(bs1, sq_r, bs2, disp, rot1, rot2, kerr);
    qnn_kernel<<<PTOT / NS, TPB, NS * SPAD * sizeof(float2)>>>(
        patches, enc_w, enc_b, ro_w, ro_b, (float*)d_out);
}